// round 9
// baseline (speedup 1.0000x reference)
#include <cuda_runtime.h>
#include <cstdint>
#include <cstddef>

#define Bn 256
#define Ln 1024
#define Vn 40
#define Hn 128
#define HPAD 136   // s_h row: half0 at [0..63], half1 at [68..131] (16B apart)
#define HOFF 68

// ---- packed f32x2 helpers (FFMA2 only reachable via PTX) ----
__device__ __forceinline__ unsigned long long ffma2(unsigned long long a,
                                                    unsigned long long b,
                                                    unsigned long long c) {
    unsigned long long d;
    asm("fma.rn.f32x2 %0, %1, %2, %3;" : "=l"(d) : "l"(a), "l"(b), "l"(c));
    return d;
}
__device__ __forceinline__ unsigned long long add2(unsigned long long a,
                                                   unsigned long long b) {
    unsigned long long d;
    asm("add.rn.f32x2 %0, %1, %2;" : "=l"(d) : "l"(a), "l"(b));
    return d;
}
__device__ __forceinline__ float plo(unsigned long long a) {
    return __int_as_float((int)(unsigned)(a & 0xffffffffull));
}
__device__ __forceinline__ float phi(unsigned long long a) {
    return __int_as_float((int)(unsigned)(a >> 32));
}
__device__ __forceinline__ float tanh_fast(float x) {
    float r;
    asm("tanh.approx.f32 %0, %1;" : "=f"(r) : "f"(x));
    return r;
}

// =====================================================================
// Fused CharRNN, intra-warp exchange version. One CTA per batch row.
// Thread t: e = t>>1 (owns h elems e, e+64), kh = t&1 (k-half).
// Partner (other k-half) is t^1 -> SAME WARP: the partial exchange is
// one SHFL.BFLY(1) instead of STS+BAR+LDS. Only ONE barrier per step
// remains (the h publish/consume handoff). kh=0 folds em+bh pre-shfl;
// kh=0 finalizes elem e, kh=1 finalizes elem e+64. Logit v=e (<40)
// rides the same registers; iteration l emits logit row l-1 (h loaded
// at iter l is the output of step l-1), row Ln-1 in an epilogue.
// =====================================================================
__global__ void __launch_bounds__(128, 2) fused_rnn_kernel(
    const int* __restrict__ x, const float* __restrict__ h0,
    const float* __restrict__ emb, const float* __restrict__ Wh,
    const float* __restrict__ Wo, const float* __restrict__ bh,
    const float* __restrict__ by, float* __restrict__ out,
    float* __restrict__ final_h)
{
    __shared__ __align__(16) float s_emb[Vn * Hn];   // 20 KB
    __shared__ int s_x[Ln];                          // 4 KB
    __shared__ __align__(16) float s_h[2][HPAD];     // ping-pong h, padded halves

    const int t  = threadIdx.x;
    const int b  = blockIdx.x;
    const int e  = t >> 1;          // owned h elems e, e+64; logit v = e
    const int kh = t & 1;           // k-half (lane-low-bit: partner in-warp)

    for (int i = t; i < Vn * Hn; i += 128) s_emb[i] = emb[i];
    for (int i = t; i < Ln; i += 128) s_x[i] = x[b * Ln + i];
    s_h[0][t < 64 ? t : t + (HOFF - 64)] = h0[b * Hn + t];
    const float bh0 = bh[e];
    const float bh1 = bh[e + 64];
    const bool  dv  = (e < Vn);
    const float byv = dv ? by[e] : 0.f;

    // wh[0..31]: Wh row e, cols [64kh,64kh+64); wh[32..63]: row e+64
    unsigned long long wh[64];
    {
        const ulonglong2* w0 = (const ulonglong2*)(Wh + e * Hn + kh * 64);
        const ulonglong2* w1 = (const ulonglong2*)(Wh + (e + 64) * Hn + kh * 64);
#pragma unroll
        for (int i = 0; i < 16; i++) {
            ulonglong2 p = w0[i];
            wh[2 * i] = p.x; wh[2 * i + 1] = p.y;
        }
#pragma unroll
        for (int i = 0; i < 16; i++) {
            ulonglong2 p = w1[i];
            wh[32 + 2 * i] = p.x; wh[33 + 2 * i] = p.y;
        }
    }
    // wo[0..31]: Wo row v=e, cols [64kh,64kh+64) (zeros if v >= 40)
    unsigned long long wo[32];
    if (dv) {
        const ulonglong2* wv = (const ulonglong2*)(Wo + e * Hn + kh * 64);
#pragma unroll
        for (int i = 0; i < 16; i++) {
            ulonglong2 p = wv[i];
            wo[2 * i] = p.x; wo[2 * i + 1] = p.y;
        }
    } else {
#pragma unroll
        for (int i = 0; i < 32; i++) wo[i] = 0ull;
    }
    __syncthreads();

    float* obase = out + (size_t)b * Ln * Vn;

    // Prefetch embedding terms for step 0 (kh=0 lanes use them)
    float em0c = 0.f, em1c = 0.f;
    {
        const int idx0 = s_x[0];
        if (kh == 0) {
            em0c = s_emb[idx0 * Hn + e];
            em1c = s_emb[idx0 * Hn + e + 64];
        }
    }

#pragma unroll 1
    for (int l = 0; l < Ln; l++) {
        // h entering step l == output of step l-1. Even lanes read half0
        // (floats 0..63), odd lanes half1 (floats 68..131) -> disjoint banks.
        const ulonglong2* hp = (const ulonglong2*)(&s_h[l & 1][kh * HOFF]);

        unsigned long long a0 = 0, a1 = 0;   // h elem e
        unsigned long long c0 = 0, c1 = 0;   // h elem e+64
        unsigned long long g0 = 0, g1 = 0;   // logit v=e (for row l-1)
#pragma unroll
        for (int i = 0; i < 16; i++) {
            ulonglong2 p = hp[i];            // LDS.128 -> feeds 6 FFMA2
            a0 = ffma2(wh[2 * i],      p.x, a0);
            c0 = ffma2(wh[32 + 2 * i], p.x, c0);
            g0 = ffma2(wo[2 * i],      p.x, g0);
            a1 = ffma2(wh[2 * i + 1],  p.y, a1);
            c1 = ffma2(wh[33 + 2 * i], p.y, c1);
            g1 = ffma2(wo[2 * i + 1],  p.y, g1);
        }
        a0 = add2(a0, a1);
        c0 = add2(c0, c1);
        g0 = add2(g0, g1);
        float pe0 = plo(a0) + phi(a0);       // elem e, my k-half
        float pe1 = plo(c0) + phi(c0);       // elem e+64, my k-half
        const float lp = plo(g0) + phi(g0);  // logit v=e, my k-half

        if (kh == 0) {                        // fold em + bh exactly once
            pe0 += em0c + bh0;
            pe1 += em1c + bh1;
        }

        // Intra-warp exchange with partner t^1 (other k-half).
        // kh0 lane sends pe1 (partner finalizes e+64), receives partner's pe0.
        const float send = kh ? pe0 : pe1;
        const float recv = __shfl_xor_sync(0xffffffffu, send, 1);
        const float lpr  = __shfl_xor_sync(0xffffffffu, lp, 1);

        const float mine = kh ? pe1 : pe0;
        const float hn = tanh_fast(mine + recv);
        s_h[(l + 1) & 1][kh ? (e + HOFF) : e] = hn;   // STS.32

        if (dv && kh == 0 && l > 0) {         // logit row l-1
            obase[(size_t)(l - 1) * Vn + e] = lp + lpr + byv;
        }

        // Register-prefetch embedding terms for step l+1 (hidden by BAR)
        {
            const int idxn = s_x[(l + 1) & (Ln - 1)];
            if (kh == 0) {
                em0c = s_emb[idxn * Hn + e];
                em1c = s_emb[idxn * Hn + e + 64];
            }
        }
        __syncthreads();                      // single per-step barrier
    }

    // Epilogue: logit row Ln-1 from the final hidden state (s_h[0]).
    {
        const ulonglong2* hp = (const ulonglong2*)(&s_h[0][kh * HOFF]);
        unsigned long long g0 = 0, g1 = 0;
#pragma unroll
        for (int i = 0; i < 16; i++) {
            ulonglong2 p = hp[i];
            g0 = ffma2(wo[2 * i],     p.x, g0);
            g1 = ffma2(wo[2 * i + 1], p.y, g1);
        }
        g0 = add2(g0, g1);
        const float lp  = plo(g0) + phi(g0);
        const float lpr = __shfl_xor_sync(0xffffffffu, lp, 1);
        if (dv && kh == 0) {
            obase[(size_t)(Ln - 1) * Vn + e] = lp + lpr + byv;
        }
    }

    // Ln even -> final state in buffer 0 (padded layout)
    final_h[b * Hn + t] = s_h[0][t < 64 ? t : t + (HOFF - 64)];
}

extern "C" void kernel_launch(void* const* d_in, const int* in_sizes, int n_in,
                              void* d_out, int out_size)
{
    const int*   x   = (const int*)d_in[0];
    const float* h0  = (const float*)d_in[1];
    const float* emb = (const float*)d_in[2];
    const float* Wh  = (const float*)d_in[3];
    const float* Wo  = (const float*)d_in[4];
    const float* bh  = (const float*)d_in[5];
    const float* by  = (const float*)d_in[6];

    float* out     = (float*)d_out;
    float* logits  = out;                               // [B, L, V]
    float* final_h = out + (size_t)Bn * Ln * Vn;        // [B, H]

    fused_rnn_kernel<<<Bn, 128>>>(x, h0, emb, Wh, Wo, bh, by, logits, final_h);
}